// round 1
// baseline (speedup 1.0000x reference)
#include <cuda_runtime.h>
#include <cstdint>
#include <cfloat>

// Problem constants (fixed shapes for MergeNN_38903813767173)
#define B_ 2048
#define N_ 20000
#define D_ 64
#define DY_ 32
#define L_ 100
#define ETA_ 0.01f

#define TJ 64                 // query columns per block
#define TI 32                 // dataset rows per chunk
#define NSLAB 25              // row slabs (N_ / NSLAB = 800 = 25 chunks of 32)
#define SLABROWS (N_ / NSLAB)
#define NCHUNK (SLABROWS / TI)

// ---------------- scratch (device globals; no allocations allowed) ----------
__device__ float g_nx[B_];
__device__ float g_ns[N_];
__device__ float g_nf1[N_];
__device__ float g_nf2[N_];
__device__ int   g_match[B_];

__device__ float g_esum_part[NSLAB][B_];
__device__ float g_acc1_part[NSLAB][B_][D_];
__device__ float g_acc2_part[NSLAB][B_][D_];

__device__ float g_xt1[B_][D_];
__device__ float g_xt2[B_][D_];
__device__ float g_nxt1[B_];
__device__ float g_nxt2[B_];
__device__ int   g_yidx1[B_];
__device__ int   g_yidx2[B_];

__device__ float g_num1_part[NSLAB][B_][DY_];
__device__ float g_num2_part[NSLAB][B_][DY_];
__device__ float g_den1_part[NSLAB][B_];
__device__ float g_den2_part[NSLAB][B_];

// ---------------- K0: squared norms + match init -----------------------------
__global__ void k_prep(const float* __restrict__ x, const float* __restrict__ star,
                       const float* __restrict__ f1, const float* __restrict__ f2) {
    int gid = blockIdx.x * blockDim.x + threadIdx.x;
    const float* src;
    float* dst;
    if (gid < B_) {
        g_match[gid] = 0x7fffffff;
        src = x + gid * D_;        dst = &g_nx[gid];
    } else if (gid < B_ + N_) {
        int r = gid - B_;          src = star + r * D_; dst = &g_ns[r];
    } else if (gid < B_ + 2 * N_) {
        int r = gid - B_ - N_;     src = f1 + r * D_;   dst = &g_nf1[r];
    } else if (gid < B_ + 3 * N_) {
        int r = gid - B_ - 2 * N_; src = f2 + r * D_;   dst = &g_nf2[r];
    } else {
        return;
    }
    float s = 0.f;
    const float4* p = reinterpret_cast<const float4*>(src);
#pragma unroll
    for (int i = 0; i < 16; i++) {
        float4 v = p[i];
        s += v.x * v.x + v.y * v.y + v.z * v.z + v.w * v.w;
    }
    *dst = s;
}

// ---------------- K1: phase A — e_star, esum, feats^T @ e_star ---------------
struct __align__(16) SmemA {
    float xst[D_][TJ];   // x tile, transposed: xst[k][j]
    float nxs[TJ];
    float ss[TI][D_];    // star chunk
    float f1s[TI][D_];
    float f2s[TI][D_];
    float nss[TI];
    float es[TI][TJ];    // e_star tile
};

__global__ __launch_bounds__(256)
void k_phaseA(const float* __restrict__ x, const float* __restrict__ star,
              const float* __restrict__ f1, const float* __restrict__ f2) {
    extern __shared__ char smem_raw[];
    SmemA& sm = *reinterpret_cast<SmemA*>(smem_raw);
    const int tid   = threadIdx.x;
    const int j0    = blockIdx.x * TJ;
    const int slab  = blockIdx.y;
    const int ibase = slab * SLABROWS;

    // load x tile (transposed) once
    for (int idx = tid; idx < TJ * D_; idx += 256) {
        int j = idx >> 6, k = idx & 63;
        sm.xst[k][j] = x[(j0 + j) * D_ + k];
    }
    if (tid < TJ) sm.nxs[tid] = g_nx[j0 + tid];

    const int jj    = tid & 63;
    const int dgrp  = tid >> 6;
    const int dbase = dgrp * 16;
    const int col4  = (tid & 15) * 4;
    const int row2  = (tid >> 4) * 2;

    float acc1r[16], acc2r[16];
    float esumr = 0.f;
#pragma unroll
    for (int i = 0; i < 16; i++) { acc1r[i] = 0.f; acc2r[i] = 0.f; }

    for (int c = 0; c < NCHUNK; c++) {
        const int i0 = ibase + c * TI;
        __syncthreads();   // protect es/f1s/f2s consumers from reload
        // load chunk (vectorized)
        for (int idx = tid; idx < TI * (D_ / 4); idx += 256) {
            int r = idx >> 4, k4 = idx & 15;
            reinterpret_cast<float4*>(sm.ss[r])[k4]  =
                reinterpret_cast<const float4*>(star + (i0 + r) * D_)[k4];
            reinterpret_cast<float4*>(sm.f1s[r])[k4] =
                reinterpret_cast<const float4*>(f1 + (i0 + r) * D_)[k4];
            reinterpret_cast<float4*>(sm.f2s[r])[k4] =
                reinterpret_cast<const float4*>(f2 + (i0 + r) * D_)[k4];
        }
        if (tid < TI) sm.nss[tid] = g_ns[i0 + tid];
        __syncthreads();

        // 2x4 micro-tile dot products
        float a[2][4];
#pragma unroll
        for (int r = 0; r < 2; r++)
#pragma unroll
            for (int cc = 0; cc < 4; cc++) a[r][cc] = 0.f;
#pragma unroll 16
        for (int k = 0; k < D_; k++) {
            float s0 = sm.ss[row2][k];
            float s1 = sm.ss[row2 + 1][k];
            float4 xv = *reinterpret_cast<const float4*>(&sm.xst[k][col4]);
            a[0][0] += s0 * xv.x; a[0][1] += s0 * xv.y; a[0][2] += s0 * xv.z; a[0][3] += s0 * xv.w;
            a[1][0] += s1 * xv.x; a[1][1] += s1 * xv.y; a[1][2] += s1 * xv.z; a[1][3] += s1 * xv.w;
        }
#pragma unroll
        for (int r = 0; r < 2; r++) {
            float ns = sm.nss[row2 + r];
            float4 ev;
            float* e4 = &ev.x;
#pragma unroll
            for (int cc = 0; cc < 4; cc++) {
                float raw = ns + sm.nxs[col4 + cc] - 2.f * a[r][cc];
                if (raw <= 0.f) atomicMin(&g_match[j0 + col4 + cc], i0 + row2 + r);
                e4[cc] = __expf(-fmaxf(raw, 0.f));
            }
            *reinterpret_cast<float4*>(&sm.es[row2 + r][col4]) = ev;
        }
        __syncthreads();

        // accumulate: acc[j][d] += f[i][d] * e[i][j]
#pragma unroll 8
        for (int i = 0; i < TI; i++) {
            float e = sm.es[i][jj];
            if (dgrp == 0) esumr += e;
#pragma unroll
            for (int q = 0; q < 4; q++) {
                float4 v1 = *reinterpret_cast<const float4*>(&sm.f1s[i][dbase + 4 * q]);
                acc1r[4 * q + 0] += v1.x * e; acc1r[4 * q + 1] += v1.y * e;
                acc1r[4 * q + 2] += v1.z * e; acc1r[4 * q + 3] += v1.w * e;
                float4 v2 = *reinterpret_cast<const float4*>(&sm.f2s[i][dbase + 4 * q]);
                acc2r[4 * q + 0] += v2.x * e; acc2r[4 * q + 1] += v2.y * e;
                acc2r[4 * q + 2] += v2.z * e; acc2r[4 * q + 3] += v2.w * e;
            }
        }
    }
#pragma unroll
    for (int q = 0; q < 16; q++) {
        g_acc1_part[slab][j0 + jj][dbase + q] = acc1r[q];
        g_acc2_part[slab][j0 + jj][dbase + q] = acc2r[q];
    }
    if (dgrp == 0) g_esum_part[slab][j0 + jj] = esumr;
}

// ---------------- K2: middle — xt, y = xt@W+b, argmin label ------------------
__global__ __launch_bounds__(128)
void k_mid(const float* __restrict__ f1, const float* __restrict__ f2,
           const float* __restrict__ W1, const float* __restrict__ b1,
           const float* __restrict__ W2, const float* __restrict__ b2,
           const float* __restrict__ u1, const float* __restrict__ u2) {
    int j = blockIdx.x;
    int t = threadIdx.x;   // 128 threads

    __shared__ float xts[D_];
    __shared__ float ys[DY_];
    __shared__ float esum_s;
    __shared__ float ny_s;
    __shared__ float redv[128];
    __shared__ int   redi[128];

    int  mi = g_match[j];
    bool hm = (mi != 0x7fffffff);
    if (t == 0) {
        float s = 0.f;
        for (int k = 0; k < NSLAB; k++) s += g_esum_part[k][j];
        esum_s = s;
    }
    __syncthreads();

    for (int br = 0; br < 2; br++) {
        const float* f  = br ? f2 : f1;
        const float* W  = br ? W2 : W1;
        const float* bb = br ? b2 : b1;
        const float* u  = br ? u2 : u1;

        if (t < D_) {
            float a = 0.f;
            if (br) { for (int k = 0; k < NSLAB; k++) a += g_acc2_part[k][j][t]; }
            else    { for (int k = 0; k < NSLAB; k++) a += g_acc1_part[k][j][t]; }
            float v = hm ? f[mi * D_ + t] : a / esum_s;
            xts[t] = v;
            if (br) g_xt2[j][t] = v; else g_xt1[j][t] = v;
        }
        __syncthreads();
        if (t == 0) {
            float s = 0.f;
            for (int d = 0; d < D_; d++) s += xts[d] * xts[d];
            if (br) g_nxt2[j] = s; else g_nxt1[j] = s;
        }
        if (t < DY_) {
            float a = bb[t];
            for (int d = 0; d < D_; d++) a += xts[d] * W[d * DY_ + t];
            ys[t] = a;
        }
        __syncthreads();
        if (t == 0) {
            float s = 0.f;
            for (int dy = 0; dy < DY_; dy++) s += ys[dy] * ys[dy];
            ny_s = s;
        }
        __syncthreads();

        float v = FLT_MAX;
        int   vi = 0x7fffffff;
        if (t < L_) {
            float nu = 0.f, dot = 0.f;
            for (int dy = 0; dy < DY_; dy++) {
                float uu = u[t * DY_ + dy];
                nu += uu * uu;
                dot += uu * ys[dy];
            }
            v = fmaxf(ny_s + nu - 2.f * dot, 0.f);
            vi = t;
        }
        redv[t] = v; redi[t] = vi;
        __syncthreads();
        for (int off = 64; off > 0; off >>= 1) {
            if (t < off) {
                float v2 = redv[t + off]; int i2 = redi[t + off];
                if (v2 < redv[t] || (v2 == redv[t] && i2 < redi[t])) {
                    redv[t] = v2; redi[t] = i2;
                }
            }
            __syncthreads();
        }
        if (t == 0) { if (br) g_yidx2[j] = redi[0]; else g_yidx1[j] = redi[0]; }
        __syncthreads();   // before xts/ys reuse next branch
    }
}

// ---------------- K3: phase C — e2, labels^T @ e2 ---------------------------
struct __align__(16) SmemC {
    float lds[L_ * L_];   // 40000 B label-distance table
    float xtst[D_][TJ];   // xt tile, transposed
    float nxts[TJ];
    int   yidxs[TJ];
    float fs[TI][D_];
    float nfs[TI];
    int   lidxs[TI];
    float sls[TI][DY_];   // star_labels chunk
    float es[TI][TJ];
};

__global__ __launch_bounds__(256)
void k_phaseC(const float* __restrict__ f1, const float* __restrict__ f2,
              const float* __restrict__ slb,
              const float* __restrict__ ld1, const float* __restrict__ ld2,
              const int* __restrict__ li1, const int* __restrict__ li2) {
    extern __shared__ char smem_raw[];
    SmemC& sm = *reinterpret_cast<SmemC*>(smem_raw);
    const int tid   = threadIdx.x;
    const int j0    = blockIdx.x * TJ;
    const int slab  = blockIdx.y;
    const int br    = blockIdx.z;
    const int ibase = slab * SLABROWS;

    const float* f   = br ? f2 : f1;
    const float* ld  = br ? ld2 : ld1;
    const int*   li  = br ? li2 : li1;
    const float* nf  = br ? g_nf2 : g_nf1;
    const float (*xt)[D_] = br ? g_xt2 : g_xt1;
    const float* nxt = br ? g_nxt2 : g_nxt1;
    const int*   yix = br ? g_yidx2 : g_yidx1;

    for (int idx = tid; idx < L_ * L_; idx += 256) sm.lds[idx] = ld[idx];
    for (int idx = tid; idx < TJ * D_; idx += 256) {
        int j = idx >> 6, k = idx & 63;
        sm.xtst[k][j] = xt[j0 + j][k];
    }
    if (tid < TJ) { sm.nxts[tid] = nxt[j0 + tid]; sm.yidxs[tid] = yix[j0 + tid]; }

    const int jj     = tid & 63;
    const int dgrp   = tid >> 6;
    const int dybase = dgrp * 8;
    const int col4   = (tid & 15) * 4;
    const int row2   = (tid >> 4) * 2;

    float numr[8];
    float denr = 0.f;
#pragma unroll
    for (int i = 0; i < 8; i++) numr[i] = 0.f;

    for (int c = 0; c < NCHUNK; c++) {
        const int i0 = ibase + c * TI;
        __syncthreads();
        for (int idx = tid; idx < TI * (D_ / 4); idx += 256) {
            int r = idx >> 4, k4 = idx & 15;
            reinterpret_cast<float4*>(sm.fs[r])[k4] =
                reinterpret_cast<const float4*>(f + (i0 + r) * D_)[k4];
        }
        for (int idx = tid; idx < TI * (DY_ / 4); idx += 256) {
            int r = idx >> 3, k4 = idx & 7;
            reinterpret_cast<float4*>(sm.sls[r])[k4] =
                reinterpret_cast<const float4*>(slb + (i0 + r) * DY_)[k4];
        }
        if (tid < TI) { sm.nfs[tid] = nf[i0 + tid]; sm.lidxs[tid] = li[i0 + tid]; }
        __syncthreads();

        float a[2][4];
#pragma unroll
        for (int r = 0; r < 2; r++)
#pragma unroll
            for (int cc = 0; cc < 4; cc++) a[r][cc] = 0.f;
#pragma unroll 16
        for (int k = 0; k < D_; k++) {
            float s0 = sm.fs[row2][k];
            float s1 = sm.fs[row2 + 1][k];
            float4 xv = *reinterpret_cast<const float4*>(&sm.xtst[k][col4]);
            a[0][0] += s0 * xv.x; a[0][1] += s0 * xv.y; a[0][2] += s0 * xv.z; a[0][3] += s0 * xv.w;
            a[1][0] += s1 * xv.x; a[1][1] += s1 * xv.y; a[1][2] += s1 * xv.z; a[1][3] += s1 * xv.w;
        }
#pragma unroll
        for (int r = 0; r < 2; r++) {
            float nfv = sm.nfs[row2 + r];
            int lrow  = sm.lidxs[row2 + r] * L_;
            float4 ev;
            float* e4 = &ev.x;
#pragma unroll
            for (int cc = 0; cc < 4; cc++) {
                float raw = nfv + sm.nxts[col4 + cc] - 2.f * a[r][cc];
                float dd  = fmaxf(raw, 0.f);
                e4[cc] = __expf(-dd - ETA_ * sm.lds[lrow + sm.yidxs[col4 + cc]]);
            }
            *reinterpret_cast<float4*>(&sm.es[row2 + r][col4]) = ev;
        }
        __syncthreads();

#pragma unroll 8
        for (int i = 0; i < TI; i++) {
            float e = sm.es[i][jj];
            if (dgrp == 0) denr += e;
            float4 v0 = *reinterpret_cast<const float4*>(&sm.sls[i][dybase]);
            float4 v1 = *reinterpret_cast<const float4*>(&sm.sls[i][dybase + 4]);
            numr[0] += v0.x * e; numr[1] += v0.y * e; numr[2] += v0.z * e; numr[3] += v0.w * e;
            numr[4] += v1.x * e; numr[5] += v1.y * e; numr[6] += v1.z * e; numr[7] += v1.w * e;
        }
    }
    if (br) {
#pragma unroll
        for (int q = 0; q < 8; q++) g_num2_part[slab][j0 + jj][dybase + q] = numr[q];
        if (dgrp == 0) g_den2_part[slab][j0 + jj] = denr;
    } else {
#pragma unroll
        for (int q = 0; q < 8; q++) g_num1_part[slab][j0 + jj][dybase + q] = numr[q];
        if (dgrp == 0) g_den1_part[slab][j0 + jj] = denr;
    }
}

// ---------------- K4: reduce partials, combine branches ----------------------
__global__ void k_out(float* __restrict__ out) {
    int gid = blockIdx.x * blockDim.x + threadIdx.x;
    if (gid >= B_ * DY_) return;
    int j = gid >> 5, dy = gid & 31;
    float n1 = 0.f, d1 = 0.f, n2 = 0.f, d2 = 0.f;
    for (int s = 0; s < NSLAB; s++) {
        n1 += g_num1_part[s][j][dy];
        d1 += g_den1_part[s][j];
        n2 += g_num2_part[s][j][dy];
        d2 += g_den2_part[s][j];
    }
    out[gid] = 0.5f * (n1 / d1 + n2 / d2);
}

// ---------------- launch -----------------------------------------------------
extern "C" void kernel_launch(void* const* d_in, const int* in_sizes, int n_in,
                              void* d_out, int out_size) {
    const float* x    = (const float*)d_in[0];
    const float* star = (const float*)d_in[1];
    const float* slb  = (const float*)d_in[2];
    const float* f1   = (const float*)d_in[3];
    const float* f2   = (const float*)d_in[4];
    const float* u1   = (const float*)d_in[5];
    const float* u2   = (const float*)d_in[6];
    const float* ld1  = (const float*)d_in[7];
    const float* ld2  = (const float*)d_in[8];
    const float* W1   = (const float*)d_in[9];
    const float* b1   = (const float*)d_in[10];
    const float* W2   = (const float*)d_in[11];
    const float* b2   = (const float*)d_in[12];
    const int*   li1  = (const int*)d_in[13];
    const int*   li2  = (const int*)d_in[14];
    float* out = (float*)d_out;

    cudaFuncSetAttribute(k_phaseA, cudaFuncAttributeMaxDynamicSharedMemorySize,
                         (int)sizeof(SmemA));
    cudaFuncSetAttribute(k_phaseC, cudaFuncAttributeMaxDynamicSharedMemorySize,
                         (int)sizeof(SmemC));

    k_prep<<<(B_ + 3 * N_ + 255) / 256, 256>>>(x, star, f1, f2);
    k_phaseA<<<dim3(B_ / TJ, NSLAB), 256, sizeof(SmemA)>>>(x, star, f1, f2);
    k_mid<<<B_, 128>>>(f1, f2, W1, b1, W2, b2, u1, u2);
    k_phaseC<<<dim3(B_ / TJ, NSLAB, 2), 256, sizeof(SmemC)>>>(f1, f2, slb, ld1, ld2, li1, li2);
    k_out<<<(B_ * DY_ + 255) / 256, 256>>>(out);
}

// round 2
// speedup vs baseline: 1.0703x; 1.0703x over previous
#include <cuda_runtime.h>
#include <cstdint>
#include <cfloat>

// Problem constants (fixed shapes for MergeNN_38903813767173)
#define B_ 2048
#define N_ 20000
#define D_ 64
#define DY_ 32
#define L_ 100
#define ETA_ 0.01f

#define TJ 64                 // query columns per block
#define TI 64                 // dataset rows per chunk
#define SLABROWS 832          // rows per slab (13 chunks of 64)
#define NSLAB 25              // ceil(20000/832)

#define SSP 65                // row-major star/f chunk stride (pad: conflict-free scalar reads)
#define XSP 68                // k-major x tile stride (pad, 16B-aligned rows)
#define ESP 68                // es tile stride

typedef unsigned long long ull;

__device__ __forceinline__ ull pack2(float lo, float hi) {
    ull r; asm("mov.b64 %0, {%1, %2};" : "=l"(r) : "f"(lo), "f"(hi)); return r;
}
__device__ __forceinline__ void unpack2(ull v, float& lo, float& hi) {
    asm("mov.b64 {%0, %1}, %2;" : "=f"(lo), "=f"(hi) : "l"(v));
}
__device__ __forceinline__ void ffma2(ull& d, ull a, ull b) {
    asm("fma.rn.f32x2 %0, %1, %2, %0;" : "+l"(d) : "l"(a), "l"(b));
}

// ---------------- scratch (device globals; no allocations allowed) ----------
__device__ float g_nx[B_];
__device__ float g_ns[N_];
__device__ float g_nf1[N_];
__device__ float g_nf2[N_];
__device__ int   g_match[B_];

__device__ float g_esum_part[NSLAB][B_];
__device__ float g_acc1_part[NSLAB][B_][D_];
__device__ float g_acc2_part[NSLAB][B_][D_];

__device__ float g_xt1[B_][D_];
__device__ float g_xt2[B_][D_];
__device__ float g_nxt1[B_];
__device__ float g_nxt2[B_];
__device__ int   g_yidx1[B_];
__device__ int   g_yidx2[B_];

__device__ float g_num1_part[NSLAB][B_][DY_];
__device__ float g_num2_part[NSLAB][B_][DY_];
__device__ float g_den1_part[NSLAB][B_];
__device__ float g_den2_part[NSLAB][B_];

// ---------------- K0: squared norms + match init -----------------------------
__global__ void k_prep(const float* __restrict__ x, const float* __restrict__ star,
                       const float* __restrict__ f1, const float* __restrict__ f2) {
    int gid = blockIdx.x * blockDim.x + threadIdx.x;
    const float* src;
    float* dst;
    if (gid < B_) {
        g_match[gid] = 0x7fffffff;
        src = x + gid * D_;        dst = &g_nx[gid];
    } else if (gid < B_ + N_) {
        int r = gid - B_;          src = star + r * D_; dst = &g_ns[r];
    } else if (gid < B_ + 2 * N_) {
        int r = gid - B_ - N_;     src = f1 + r * D_;   dst = &g_nf1[r];
    } else if (gid < B_ + 3 * N_) {
        int r = gid - B_ - 2 * N_; src = f2 + r * D_;   dst = &g_nf2[r];
    } else {
        return;
    }
    float s = 0.f;
    const float4* p = reinterpret_cast<const float4*>(src);
#pragma unroll
    for (int i = 0; i < 16; i++) {
        float4 v = p[i];
        s += v.x * v.x + v.y * v.y + v.z * v.z + v.w * v.w;
    }
    *dst = s;
}

// ---------------- K1: phase A — e_star, esum, feats^T @ e_star ---------------
struct __align__(16) SmemA {
    float xst[D_][XSP];   // x tile, k-major: xst[k][j]
    float nxs[TJ];
    float ss[TI][SSP];    // star chunk, row-major (padded)
    float nss[TI];
    float f1s[TI][D_];
    float f2s[TI][D_];
    float es[TI][ESP];    // e_star tile [i][j]
};

__global__ __launch_bounds__(128)
void k_phaseA(const float* __restrict__ x, const float* __restrict__ star,
              const float* __restrict__ f1, const float* __restrict__ f2) {
    extern __shared__ char raw_[];
    SmemA& sm = *reinterpret_cast<SmemA*>(raw_);
    const int tid   = threadIdx.x;
    const int j0    = blockIdx.x * TJ;
    const int slab  = blockIdx.y;
    const int ibase = slab * SLABROWS;
    const int iend  = min(ibase + SLABROWS, N_);

    // load x tile transposed (k-major), once per block
    for (int idx = tid; idx < TJ * (D_ / 4); idx += 128) {
        int j = idx >> 4, k4 = (idx & 15) * 4;
        float4 v = *reinterpret_cast<const float4*>(x + (j0 + j) * D_ + k4);
        sm.xst[k4 + 0][j] = v.x; sm.xst[k4 + 1][j] = v.y;
        sm.xst[k4 + 2][j] = v.z; sm.xst[k4 + 3][j] = v.w;
    }
    if (tid < TJ) sm.nxs[tid] = g_nx[j0 + tid];

    const int cg = tid & 7,    col8 = cg * 8;     // distance: 8 cols
    const int rg = tid >> 3,   row4 = rg * 4;     // distance: 4 rows
    const int jgrp = tid & 15, jc4 = jgrp * 4;    // accumulate: 4 cols
    const int dgrp = tid >> 4, db8 = dgrp * 8;    // accumulate: 8 d's

    ull acc1[4][4], acc2[4][4];  // [j][d-pair]
    float es0 = 0.f, es1 = 0.f, es2 = 0.f, es3 = 0.f;
#pragma unroll
    for (int a = 0; a < 4; a++)
#pragma unroll
        for (int b = 0; b < 4; b++) { acc1[a][b] = 0ull; acc2[a][b] = 0ull; }

    for (int i0 = ibase; i0 < iend; i0 += TI) {
        __syncthreads();
        for (int idx = tid; idx < TI * (D_ / 4); idx += 128) {
            int r = idx >> 4, k4 = (idx & 15) * 4;
            int gi = min(i0 + r, N_ - 1);
            float4 sv = *reinterpret_cast<const float4*>(star + gi * D_ + k4);
            sm.ss[r][k4 + 0] = sv.x; sm.ss[r][k4 + 1] = sv.y;
            sm.ss[r][k4 + 2] = sv.z; sm.ss[r][k4 + 3] = sv.w;
            *reinterpret_cast<float4*>(&sm.f1s[r][k4]) =
                *reinterpret_cast<const float4*>(f1 + gi * D_ + k4);
            *reinterpret_cast<float4*>(&sm.f2s[r][k4]) =
                *reinterpret_cast<const float4*>(f2 + gi * D_ + k4);
        }
        if (tid < TI) sm.nss[tid] = g_ns[min(i0 + tid, N_ - 1)];
        __syncthreads();

        // --- distance micro-kernel: 4 rows x 8 cols per thread, packed f32x2 ---
        ull a_[4][4];
#pragma unroll
        for (int r = 0; r < 4; r++)
#pragma unroll
            for (int c = 0; c < 4; c++) a_[r][c] = 0ull;

#pragma unroll 8
        for (int k = 0; k < D_; k++) {
            ulonglong2 xq0 = *reinterpret_cast<const ulonglong2*>(&sm.xst[k][col8]);
            ulonglong2 xq1 = *reinterpret_cast<const ulonglong2*>(&sm.xst[k][col8 + 4]);
#pragma unroll
            for (int r = 0; r < 4; r++) {
                float s = sm.ss[row4 + r][k];
                ull sp = pack2(s, s);
                ffma2(a_[r][0], sp, xq0.x);
                ffma2(a_[r][1], sp, xq0.y);
                ffma2(a_[r][2], sp, xq1.x);
                ffma2(a_[r][3], sp, xq1.y);
            }
        }

        float4 nxa = *reinterpret_cast<const float4*>(&sm.nxs[col8]);
        float4 nxb = *reinterpret_cast<const float4*>(&sm.nxs[col8 + 4]);
        float nx[8] = {nxa.x, nxa.y, nxa.z, nxa.w, nxb.x, nxb.y, nxb.z, nxb.w};
#pragma unroll
        for (int r = 0; r < 4; r++) {
            int gi = i0 + row4 + r;
            bool valid = gi < N_;
            float ns = sm.nss[row4 + r];
            float ev[8];
#pragma unroll
            for (int c2 = 0; c2 < 4; c2++) {
                float d0, d1;
                unpack2(a_[r][c2], d0, d1);
                float r0 = ns + nx[2 * c2]     - 2.f * d0;
                float r1 = ns + nx[2 * c2 + 1] - 2.f * d1;
                if (valid && r0 <= 0.f) atomicMin(&g_match[j0 + col8 + 2 * c2], gi);
                if (valid && r1 <= 0.f) atomicMin(&g_match[j0 + col8 + 2 * c2 + 1], gi);
                ev[2 * c2]     = valid ? __expf(-fmaxf(r0, 0.f)) : 0.f;
                ev[2 * c2 + 1] = valid ? __expf(-fmaxf(r1, 0.f)) : 0.f;
            }
            *reinterpret_cast<float4*>(&sm.es[row4 + r][col8]) =
                make_float4(ev[0], ev[1], ev[2], ev[3]);
            *reinterpret_cast<float4*>(&sm.es[row4 + r][col8 + 4]) =
                make_float4(ev[4], ev[5], ev[6], ev[7]);
        }
        __syncthreads();

        // --- accumulate: acc[j][d] += f[i][d] * e[i][j], 4j x 8d per thread ---
#pragma unroll 2
        for (int ii = 0; ii < TI; ii++) {
            float4 e4 = *reinterpret_cast<const float4*>(&sm.es[ii][jc4]);
            ull er[4] = {pack2(e4.x, e4.x), pack2(e4.y, e4.y),
                         pack2(e4.z, e4.z), pack2(e4.w, e4.w)};
            ulonglong2 fq0 = *reinterpret_cast<const ulonglong2*>(&sm.f1s[ii][db8]);
            ulonglong2 fq1 = *reinterpret_cast<const ulonglong2*>(&sm.f1s[ii][db8 + 4]);
#pragma unroll
            for (int j = 0; j < 4; j++) {
                ffma2(acc1[j][0], er[j], fq0.x);
                ffma2(acc1[j][1], er[j], fq0.y);
                ffma2(acc1[j][2], er[j], fq1.x);
                ffma2(acc1[j][3], er[j], fq1.y);
            }
            ulonglong2 gq0 = *reinterpret_cast<const ulonglong2*>(&sm.f2s[ii][db8]);
            ulonglong2 gq1 = *reinterpret_cast<const ulonglong2*>(&sm.f2s[ii][db8 + 4]);
#pragma unroll
            for (int j = 0; j < 4; j++) {
                ffma2(acc2[j][0], er[j], gq0.x);
                ffma2(acc2[j][1], er[j], gq0.y);
                ffma2(acc2[j][2], er[j], gq1.x);
                ffma2(acc2[j][3], er[j], gq1.y);
            }
            if (dgrp == 0) { es0 += e4.x; es1 += e4.y; es2 += e4.z; es3 += e4.w; }
        }
    }

#pragma unroll
    for (int j = 0; j < 4; j++) {
        int jj = j0 + jc4 + j;
        float o[8];
        unpack2(acc1[j][0], o[0], o[1]); unpack2(acc1[j][1], o[2], o[3]);
        unpack2(acc1[j][2], o[4], o[5]); unpack2(acc1[j][3], o[6], o[7]);
        *reinterpret_cast<float4*>(&g_acc1_part[slab][jj][db8]) =
            make_float4(o[0], o[1], o[2], o[3]);
        *reinterpret_cast<float4*>(&g_acc1_part[slab][jj][db8 + 4]) =
            make_float4(o[4], o[5], o[6], o[7]);
        unpack2(acc2[j][0], o[0], o[1]); unpack2(acc2[j][1], o[2], o[3]);
        unpack2(acc2[j][2], o[4], o[5]); unpack2(acc2[j][3], o[6], o[7]);
        *reinterpret_cast<float4*>(&g_acc2_part[slab][jj][db8]) =
            make_float4(o[0], o[1], o[2], o[3]);
        *reinterpret_cast<float4*>(&g_acc2_part[slab][jj][db8 + 4]) =
            make_float4(o[4], o[5], o[6], o[7]);
    }
    if (dgrp == 0) {
        g_esum_part[slab][j0 + jc4 + 0] = es0;
        g_esum_part[slab][j0 + jc4 + 1] = es1;
        g_esum_part[slab][j0 + jc4 + 2] = es2;
        g_esum_part[slab][j0 + jc4 + 3] = es3;
    }
}

// ---------------- K2: middle — xt, y = xt@W+b, argmin label ------------------
__global__ __launch_bounds__(128)
void k_mid(const float* __restrict__ f1, const float* __restrict__ f2,
           const float* __restrict__ W1, const float* __restrict__ b1,
           const float* __restrict__ W2, const float* __restrict__ b2,
           const float* __restrict__ u1, const float* __restrict__ u2) {
    int j = blockIdx.x;
    int t = threadIdx.x;   // 128 threads

    __shared__ float xts[D_];
    __shared__ float ys[DY_];
    __shared__ float esum_s;
    __shared__ float ny_s;
    __shared__ float redv[128];
    __shared__ int   redi[128];

    int  mi = g_match[j];
    bool hm = (mi != 0x7fffffff);
    if (t == 0) {
        float s = 0.f;
        for (int k = 0; k < NSLAB; k++) s += g_esum_part[k][j];
        esum_s = s;
    }
    __syncthreads();

    for (int br = 0; br < 2; br++) {
        const float* f  = br ? f2 : f1;
        const float* W  = br ? W2 : W1;
        const float* bb = br ? b2 : b1;
        const float* u  = br ? u2 : u1;

        if (t < D_) {
            float a = 0.f;
            if (br) { for (int k = 0; k < NSLAB; k++) a += g_acc2_part[k][j][t]; }
            else    { for (int k = 0; k < NSLAB; k++) a += g_acc1_part[k][j][t]; }
            float v = hm ? f[mi * D_ + t] : a / esum_s;
            xts[t] = v;
            if (br) g_xt2[j][t] = v; else g_xt1[j][t] = v;
        }
        __syncthreads();
        if (t == 0) {
            float s = 0.f;
            for (int d = 0; d < D_; d++) s += xts[d] * xts[d];
            if (br) g_nxt2[j] = s; else g_nxt1[j] = s;
        }
        if (t < DY_) {
            float a = bb[t];
            for (int d = 0; d < D_; d++) a += xts[d] * W[d * DY_ + t];
            ys[t] = a;
        }
        __syncthreads();
        if (t == 0) {
            float s = 0.f;
            for (int dy = 0; dy < DY_; dy++) s += ys[dy] * ys[dy];
            ny_s = s;
        }
        __syncthreads();

        float v = FLT_MAX;
        int   vi = 0x7fffffff;
        if (t < L_) {
            float nu = 0.f, dot = 0.f;
            for (int dy = 0; dy < DY_; dy++) {
                float uu = u[t * DY_ + dy];
                nu += uu * uu;
                dot += uu * ys[dy];
            }
            v = fmaxf(ny_s + nu - 2.f * dot, 0.f);
            vi = t;
        }
        redv[t] = v; redi[t] = vi;
        __syncthreads();
        for (int off = 64; off > 0; off >>= 1) {
            if (t < off) {
                float v2 = redv[t + off]; int i2 = redi[t + off];
                if (v2 < redv[t] || (v2 == redv[t] && i2 < redi[t])) {
                    redv[t] = v2; redi[t] = i2;
                }
            }
            __syncthreads();
        }
        if (t == 0) { if (br) g_yidx2[j] = redi[0]; else g_yidx1[j] = redi[0]; }
        __syncthreads();
    }
}

// ---------------- K3: phase C — e2, labels^T @ e2 ---------------------------
struct __align__(16) SmemC {
    float lds[L_ * L_];   // 40000 B label-distance table
    float xtst[D_][XSP];  // xt tile, k-major
    float nxts[TJ];
    int   yidxs[TJ];
    float fs[TI][SSP];    // feature chunk, row-major (padded)
    float nfs[TI];
    int   lidxs[TI];
    float sls[TI][DY_];   // star_labels chunk
    float es[TI][ESP];
};

__global__ __launch_bounds__(128)
void k_phaseC(const float* __restrict__ f1, const float* __restrict__ f2,
              const float* __restrict__ slb,
              const float* __restrict__ ld1, const float* __restrict__ ld2,
              const int* __restrict__ li1, const int* __restrict__ li2) {
    extern __shared__ char raw_[];
    SmemC& sm = *reinterpret_cast<SmemC*>(raw_);
    const int tid   = threadIdx.x;
    const int j0    = blockIdx.x * TJ;
    const int slab  = blockIdx.y;
    const int br    = blockIdx.z;
    const int ibase = slab * SLABROWS;
    const int iend  = min(ibase + SLABROWS, N_);

    const float* f   = br ? f2 : f1;
    const float* ld  = br ? ld2 : ld1;
    const int*   li  = br ? li2 : li1;
    const float* nf  = br ? g_nf2 : g_nf1;
    const float (*xt)[D_] = br ? g_xt2 : g_xt1;
    const float* nxt = br ? g_nxt2 : g_nxt1;
    const int*   yix = br ? g_yidx2 : g_yidx1;
    float (*nump)[B_][DY_] = br ? g_num2_part : g_num1_part;
    float (*denp)[B_]      = br ? g_den2_part : g_den1_part;

    for (int idx = tid; idx < (L_ * L_) / 4; idx += 128)
        *reinterpret_cast<float4*>(&sm.lds[idx * 4]) =
            *reinterpret_cast<const float4*>(ld + idx * 4);
    for (int idx = tid; idx < TJ * (D_ / 4); idx += 128) {
        int j = idx >> 4, k4 = (idx & 15) * 4;
        float4 v = *reinterpret_cast<const float4*>(&xt[j0 + j][k4]);
        sm.xtst[k4 + 0][j] = v.x; sm.xtst[k4 + 1][j] = v.y;
        sm.xtst[k4 + 2][j] = v.z; sm.xtst[k4 + 3][j] = v.w;
    }
    if (tid < TJ) { sm.nxts[tid] = nxt[j0 + tid]; sm.yidxs[tid] = yix[j0 + tid]; }

    const int cg = tid & 7,    col8 = cg * 8;
    const int rg = tid >> 3,   row4 = rg * 4;
    const int jgrp = tid & 15, jc4 = jgrp * 4;
    const int dygrp = tid >> 4, dy4 = dygrp * 4;

    ull accn[4][2];
    float dn0 = 0.f, dn1 = 0.f, dn2 = 0.f, dn3 = 0.f;
#pragma unroll
    for (int a = 0; a < 4; a++) { accn[a][0] = 0ull; accn[a][1] = 0ull; }

    for (int i0 = ibase; i0 < iend; i0 += TI) {
        __syncthreads();
        for (int idx = tid; idx < TI * (D_ / 4); idx += 128) {
            int r = idx >> 4, k4 = (idx & 15) * 4;
            int gi = min(i0 + r, N_ - 1);
            float4 fv = *reinterpret_cast<const float4*>(f + gi * D_ + k4);
            sm.fs[r][k4 + 0] = fv.x; sm.fs[r][k4 + 1] = fv.y;
            sm.fs[r][k4 + 2] = fv.z; sm.fs[r][k4 + 3] = fv.w;
        }
        for (int idx = tid; idx < TI * (DY_ / 4); idx += 128) {
            int r = idx >> 3, k4 = (idx & 7) * 4;
            int gi = min(i0 + r, N_ - 1);
            *reinterpret_cast<float4*>(&sm.sls[r][k4]) =
                *reinterpret_cast<const float4*>(slb + gi * DY_ + k4);
        }
        if (tid < TI) {
            int gi = min(i0 + tid, N_ - 1);
            sm.nfs[tid] = nf[gi];
            sm.lidxs[tid] = li[gi];
        }
        __syncthreads();

        ull a_[4][4];
#pragma unroll
        for (int r = 0; r < 4; r++)
#pragma unroll
            for (int c = 0; c < 4; c++) a_[r][c] = 0ull;

#pragma unroll 8
        for (int k = 0; k < D_; k++) {
            ulonglong2 xq0 = *reinterpret_cast<const ulonglong2*>(&sm.xtst[k][col8]);
            ulonglong2 xq1 = *reinterpret_cast<const ulonglong2*>(&sm.xtst[k][col8 + 4]);
#pragma unroll
            for (int r = 0; r < 4; r++) {
                float s = sm.fs[row4 + r][k];
                ull sp = pack2(s, s);
                ffma2(a_[r][0], sp, xq0.x);
                ffma2(a_[r][1], sp, xq0.y);
                ffma2(a_[r][2], sp, xq1.x);
                ffma2(a_[r][3], sp, xq1.y);
            }
        }

        float4 nxa = *reinterpret_cast<const float4*>(&sm.nxts[col8]);
        float4 nxb = *reinterpret_cast<const float4*>(&sm.nxts[col8 + 4]);
        float nx[8] = {nxa.x, nxa.y, nxa.z, nxa.w, nxb.x, nxb.y, nxb.z, nxb.w};
        int4 yqa = *reinterpret_cast<const int4*>(&sm.yidxs[col8]);
        int4 yqb = *reinterpret_cast<const int4*>(&sm.yidxs[col8 + 4]);
        int ya[8] = {yqa.x, yqa.y, yqa.z, yqa.w, yqb.x, yqb.y, yqb.z, yqb.w};
#pragma unroll
        for (int r = 0; r < 4; r++) {
            int gi = i0 + row4 + r;
            bool valid = gi < N_;
            float nfv = sm.nfs[row4 + r];
            int lrow = sm.lidxs[row4 + r] * L_;
            float ev[8];
#pragma unroll
            for (int c2 = 0; c2 < 4; c2++) {
                float d0, d1;
                unpack2(a_[r][c2], d0, d1);
                float r0 = fmaxf(nfv + nx[2 * c2]     - 2.f * d0, 0.f);
                float r1 = fmaxf(nfv + nx[2 * c2 + 1] - 2.f * d1, 0.f);
                ev[2 * c2]     = valid ? __expf(-r0 - ETA_ * sm.lds[lrow + ya[2 * c2]])     : 0.f;
                ev[2 * c2 + 1] = valid ? __expf(-r1 - ETA_ * sm.lds[lrow + ya[2 * c2 + 1]]) : 0.f;
            }
            *reinterpret_cast<float4*>(&sm.es[row4 + r][col8]) =
                make_float4(ev[0], ev[1], ev[2], ev[3]);
            *reinterpret_cast<float4*>(&sm.es[row4 + r][col8 + 4]) =
                make_float4(ev[4], ev[5], ev[6], ev[7]);
        }
        __syncthreads();

        // accumulate: num[j][dy] += sl[i][dy] * e[i][j], 4j x 4dy per thread
#pragma unroll 4
        for (int ii = 0; ii < TI; ii++) {
            float4 e4 = *reinterpret_cast<const float4*>(&sm.es[ii][jc4]);
            ull er[4] = {pack2(e4.x, e4.x), pack2(e4.y, e4.y),
                         pack2(e4.z, e4.z), pack2(e4.w, e4.w)};
            ulonglong2 slq = *reinterpret_cast<const ulonglong2*>(&sm.sls[ii][dy4]);
#pragma unroll
            for (int j = 0; j < 4; j++) {
                ffma2(accn[j][0], er[j], slq.x);
                ffma2(accn[j][1], er[j], slq.y);
            }
            if (dygrp == 0) { dn0 += e4.x; dn1 += e4.y; dn2 += e4.z; dn3 += e4.w; }
        }
    }

#pragma unroll
    for (int j = 0; j < 4; j++) {
        int jj = j0 + jc4 + j;
        float o[4];
        unpack2(accn[j][0], o[0], o[1]);
        unpack2(accn[j][1], o[2], o[3]);
        *reinterpret_cast<float4*>(&nump[slab][jj][dy4]) =
            make_float4(o[0], o[1], o[2], o[3]);
    }
    if (dygrp == 0) {
        denp[slab][j0 + jc4 + 0] = dn0;
        denp[slab][j0 + jc4 + 1] = dn1;
        denp[slab][j0 + jc4 + 2] = dn2;
        denp[slab][j0 + jc4 + 3] = dn3;
    }
}

// ---------------- K4: reduce partials, combine branches ----------------------
__global__ void k_out(float* __restrict__ out) {
    int gid = blockIdx.x * blockDim.x + threadIdx.x;
    if (gid >= B_ * DY_) return;
    int j = gid >> 5, dy = gid & 31;
    float n1 = 0.f, d1 = 0.f, n2 = 0.f, d2 = 0.f;
    for (int s = 0; s < NSLAB; s++) {
        n1 += g_num1_part[s][j][dy];
        d1 += g_den1_part[s][j];
        n2 += g_num2_part[s][j][dy];
        d2 += g_den2_part[s][j];
    }
    out[gid] = 0.5f * (n1 / d1 + n2 / d2);
}

// ---------------- launch -----------------------------------------------------
extern "C" void kernel_launch(void* const* d_in, const int* in_sizes, int n_in,
                              void* d_out, int out_size) {
    const float* x    = (const float*)d_in[0];
    const float* star = (const float*)d_in[1];
    const float* slb  = (const float*)d_in[2];
    const float* f1   = (const float*)d_in[3];
    const float* f2   = (const float*)d_in[4];
    const float* u1   = (const float*)d_in[5];
    const float* u2   = (const float*)d_in[6];
    const float* ld1  = (const float*)d_in[7];
    const float* ld2  = (const float*)d_in[8];
    const float* W1   = (const float*)d_in[9];
    const float* b1   = (const float*)d_in[10];
    const float* W2   = (const float*)d_in[11];
    const float* b2   = (const float*)d_in[12];
    const int*   li1  = (const int*)d_in[13];
    const int*   li2  = (const int*)d_in[14];
    float* out = (float*)d_out;

    cudaFuncSetAttribute(k_phaseA, cudaFuncAttributeMaxDynamicSharedMemorySize,
                         (int)sizeof(SmemA));
    cudaFuncSetAttribute(k_phaseC, cudaFuncAttributeMaxDynamicSharedMemorySize,
                         (int)sizeof(SmemC));

    k_prep<<<(B_ + 3 * N_ + 255) / 256, 256>>>(x, star, f1, f2);
    k_phaseA<<<dim3(B_ / TJ, NSLAB), 128, sizeof(SmemA)>>>(x, star, f1, f2);
    k_mid<<<B_, 128>>>(f1, f2, W1, b1, W2, b2, u1, u2);
    k_phaseC<<<dim3(B_ / TJ, NSLAB, 2), 128, sizeof(SmemC)>>>(f1, f2, slb, ld1, ld2, li1, li2);
    k_out<<<(B_ * DY_ + 255) / 256, 256>>>(out);
}